// round 14
// baseline (speedup 1.0000x reference)
#include <cuda_runtime.h>
#include <cuda_fp16.h>
#include <mma.h>
#include <cstdint>
#include <math.h>

using namespace nvcuda;

// ---------------------------------------------------------------------------
// Problem constants
// ---------------------------------------------------------------------------
#define BVAL 4
#define SVAL 2048
#define DVAL 1024
constexpr int    BS   = BVAL * SVAL;                     // 8192 rows / modality
constexpr size_t PM   = (size_t)BS * DVAL;               // 8,388,608 / modality
constexpr size_t QKVE = 3 * PM;                          // 25,165,824
constexpr size_t SCE  = (size_t)3 * BVAL * SVAL * SVAL;  // 50,331,648

// ---------------------------------------------------------------------------
// Static device scratch. Single-pass fp16; scores now fp16 too.
// ---------------------------------------------------------------------------
__device__ __half g_Xhi[QKVE];
__device__ __half g_Qhi[QKVE];
__device__ __half g_Khi[QKVE];
__device__ __half g_Vthi[QKVE];                          // V^T: [m][1024][8192]
__device__ __half g_Ctxhi[QKVE];
__device__ __half g_Phi[SCE];
__device__ __half g_Sc[SCE];                             // fp16 scores
__device__ __half g_WqThi[3*1024*1024];
__device__ __half g_WkThi[3*1024*1024];
__device__ __half g_WvThi[3*1024*1024];
__device__ __half g_WoThi[3*1024*2048];

__device__ __forceinline__ uint32_t smem_u32(const void* p) {
    uint32_t a;
    asm("{ .reg .u64 t; cvta.to.shared.u64 t, %1; cvt.u32.u64 %0, t; }"
        : "=r"(a) : "l"(p));
    return a;
}

__device__ __forceinline__ void cpa16(uint32_t dst, const void* src) {
    asm volatile("cp.async.cg.shared.global [%0], [%1], 16;"
                 :: "r"(dst), "l"(src) : "memory");
}

// ---------------------------------------------------------------------------
// Generic 128x128 GEMM on WMMA (m16n16k16, f32 accum), single-pass fp16:
//   C = sum_seg A[seg] @ B[seg]^T
// A[seg]: M x segK row-major (lda); B[seg]: N x segK row-major (ldb).
// 256 threads = 8 warps (4x2); warp tile 32x64.
// 32-K superchunks: each stage = two 16-K sub-tiles per operand at 48B pitch
// (conflict-free ldmatrix: 48*r mod 128 distinct for r=0..7).
// Stage layout: A0 @0, A1 @6K, B0 @12K, B1 @18K -> 24 KB/stage.
// 3-stage ring in 72 KB DYNAMIC smem; ONE barrier per 32-K (half of R13),
// prefetch depth 2 superchunks (64-K). Ring safety: issue(sc+2) overwrites
// stage (sc-1)%3 whose readers all passed this iteration's __syncthreads.
// Epilogue staging overlays the same SMEM (ld=68 pad).
// Epi(row, col, v0, v1) consumes 2 adjacent columns. segK multiple of 32.
// ---------------------------------------------------------------------------
constexpr int LDT = 24;                 // tile row pitch in halves (48 bytes)
constexpr unsigned STAGE_B = 24576;     // bytes per stage
constexpr unsigned GSMEM   = 3 * STAGE_B;   // 73728 bytes dynamic

template <class Epi>
__device__ void hgemm(const __half* const* Ah, const __half* const* Bh,
                      int nseg, int segK, size_t lda, size_t ldb, Epi epi)
{
    extern __shared__ __align__(16) unsigned char smraw[];
    float* stage = reinterpret_cast<float*>(smraw);        // epilogue overlay
    const uint32_t sb = smem_u32(smraw);

    const int tid  = threadIdx.x;
    const int lane = tid & 31;
    const int wid  = tid >> 5;
    const int wm   = wid >> 1;        // 0..3 (M groups of 32)
    const int wn   = wid & 1;         // 0..1 (N groups of 64)
    const int rowBase = blockIdx.y * 128;
    const int colBase = blockIdx.x * 128;

    wmma::fragment<wmma::accumulator, 16, 16, 16, float> acc[2][4];
#pragma unroll
    for (int mt = 0; mt < 2; mt++)
#pragma unroll
        for (int nt = 0; nt < 4; nt++) wmma::fill_fragment(acc[mt][nt], 0.0f);

    const int superPerSeg = segK >> 5;
    const int nSuper = nseg * superPerSeg;

    // loader: per 16-K sub-tile, thread covers (row = tid>>1, sub = tid&1)
    const int lr = tid >> 1;
    const int ls = tid & 1;
    const uint32_t loff = (uint32_t)(lr * 48 + ls * 16);

    auto issue = [&](int sc) {
        const int s   = sc % 3;
        const int seg = sc / superPerSeg;
        const int kk  = (sc - seg * superPerSeg) << 5;     // 32-K base
        const uint32_t base = sb + (uint32_t)s * STAGE_B;
        const __half* Ap = Ah[seg] + (size_t)(rowBase + lr) * lda + kk + ls * 8;
        const __half* Bp = Bh[seg] + (size_t)(colBase + lr) * ldb + kk + ls * 8;
        cpa16(base +          loff, Ap);          // A sub 0
        cpa16(base +  6144u + loff, Ap + 16);     // A sub 1
        cpa16(base + 12288u + loff, Bp);          // B sub 0
        cpa16(base + 18432u + loff, Bp + 16);     // B sub 1
        asm volatile("cp.async.commit_group;" ::: "memory");
    };

    issue(0);
    if (nSuper > 1) issue(1);

    for (int sc = 0; sc < nSuper; sc++) {
        if (sc + 1 < nSuper)
            asm volatile("cp.async.wait_group 1;" ::: "memory");
        else
            asm volatile("cp.async.wait_group 0;" ::: "memory");
        __syncthreads();   // stage sc visible; compute(sc-1) finished by all

        __half* st0 = reinterpret_cast<__half*>(smraw + (sc % 3) * STAGE_B);

#pragma unroll
        for (int k = 0; k < 2; k++) {
            __half* sA = st0 + k * 3072;          // A0 / A1 (6 KB apart)
            __half* sB = st0 + 6144 + k * 3072;   // B0 / B1

            wmma::fragment<wmma::matrix_a, 16, 16, 16, __half, wmma::row_major> fah[2];
#pragma unroll
            for (int mt = 0; mt < 2; mt++) {
                const int r = wm * 32 + mt * 16;
                wmma::load_matrix_sync(fah[mt], sA + r * LDT, LDT);
            }
#pragma unroll
            for (int nt = 0; nt < 4; nt++) {
                wmma::fragment<wmma::matrix_b, 16, 16, 16, __half, wmma::col_major> fbh;
                const int n = wn * 64 + nt * 16;
                wmma::load_matrix_sync(fbh, sB + n * LDT, LDT);
#pragma unroll
                for (int mt = 0; mt < 2; mt++)
                    wmma::mma_sync(acc[mt][nt], fah[mt], fbh, acc[mt][nt]);
            }
        }

        if (sc + 2 < nSuper) issue(sc + 2);
    }

    // epilogue via staging overlay: warp-private 16x64 f32 region, ld=68 pad
    __syncthreads();   // all compute done before tiles are overwritten
    float* st = stage + wid * 1088;   // 16*68 floats per warp
#pragma unroll
    for (int mt = 0; mt < 2; mt++) {
#pragma unroll
        for (int nt = 0; nt < 4; nt++)
            wmma::store_matrix_sync(st + nt * 16, acc[mt][nt], 68, wmma::mem_row_major);
        __syncwarp();
#pragma unroll
        for (int j = 0; j < 16; j++) {
            float2 v = *reinterpret_cast<float2*>(st + j * 68 + 2 * lane);
            epi(rowBase + wm * 32 + mt * 16 + j, colBase + wn * 64 + 2 * lane, v.x, v.y);
        }
        __syncwarp();
    }
}

// ---------------------------------------------------------------------------
// Conversion: X (fp32) -> Xhi  [m][8192][1024]
// ---------------------------------------------------------------------------
__global__ __launch_bounds__(256)
void conv_x(const float* __restrict__ x1, const float* __restrict__ x2,
            const float* __restrict__ x3)
{
    size_t t = (size_t)blockIdx.x * blockDim.x + threadIdx.x;   // float4 index
    const size_t PM4 = PM / 4;
    int m = (int)(t / PM4);
    size_t i = t - (size_t)m * PM4;
    const float* X = (m == 0) ? x1 : (m == 1) ? x2 : x3;
    float4 v = reinterpret_cast<const float4*>(X)[i];
    size_t o = (size_t)m * PM + i * 4;
    __half2* ph = reinterpret_cast<__half2*>(g_Xhi + o);
    ph[0] = __halves2half2(__float2half_rn(v.x), __float2half_rn(v.y));
    ph[1] = __halves2half2(__float2half_rn(v.z), __float2half_rn(v.w));
}

// ---------------------------------------------------------------------------
// Transpose + convert weights: W[m][rows][cols] -> WT[m][cols][rows] fp16.
// Destinations resolved IN DEVICE CODE via `sel` (0=Wq,1=Wk,2=Wv,3=Wo) —
// host-passed __device__ symbols resolve to the host shadow (R4-R7 bug).
// ---------------------------------------------------------------------------
__global__ void convT_sel(const float* __restrict__ W, int sel, int rows, int cols)
{
    __half* hi;
    switch (sel) {
        case 0:  hi = g_WqThi; break;
        case 1:  hi = g_WkThi; break;
        case 2:  hi = g_WvThi; break;
        default: hi = g_WoThi; break;
    }
    __shared__ float tile[32][33];
    const float* Wm = W + (size_t)blockIdx.z * rows * cols;
    const int c0 = blockIdx.x * 32, r0 = blockIdx.y * 32;
    const int tx = threadIdx.x;
    for (int dy = threadIdx.y; dy < 32; dy += 8)
        tile[dy][tx] = Wm[(size_t)(r0 + dy) * cols + c0 + tx];
    __syncthreads();
    const size_t ob = (size_t)blockIdx.z * rows * cols;
    for (int dy = threadIdx.y; dy < 32; dy += 8) {
        size_t o = ob + (size_t)(c0 + dy) * rows + r0 + tx;
        hi[o] = __float2half_rn(tile[tx][dy]);
    }
}

// ---------------------------------------------------------------------------
// Q/K projections. z = m*2 + t (t: 0=Q, 1=K).  M=8192, N=1024, K=1024
// ---------------------------------------------------------------------------
__global__ __launch_bounds__(256)
void qk_proj(const float* __restrict__ bq, const float* __restrict__ bk)
{
    const int z = blockIdx.z;
    const int m = z >> 1, t = z & 1;
    const __half* Ah[1] = {g_Xhi + (size_t)m * PM};
    const __half* Bh[1] = {(t ? g_WkThi : g_WqThi) + (size_t)m * 1024 * 1024};
    const float* bias = (t ? bk : bq) + m * 1024;
    __half* Ch = (t ? g_Khi : g_Qhi) + (size_t)m * PM;

    hgemm(Ah, Bh, 1, 1024, 1024, 1024,
        [=](int r, int c, float v0, float v1) {
            size_t o = (size_t)r * 1024 + c;
            *reinterpret_cast<__half2*>(Ch + o) =
                __halves2half2(__float2half_rn(v0 + bias[c]),
                               __float2half_rn(v1 + bias[c + 1]));
        });
}

// ---------------------------------------------------------------------------
// V^T projection: Vt[m] = WvT[m] @ X[m]^T + bv.  M=1024(d), N=8192(tok), K=1024
// ---------------------------------------------------------------------------
__global__ __launch_bounds__(256)
void vt_proj(const float* __restrict__ bv)
{
    const int m = blockIdx.z;
    const __half* Ah[1] = {g_WvThi + (size_t)m * 1024 * 1024};
    const __half* Bh[1] = {g_Xhi + (size_t)m * PM};
    const float* bias = bv + m * 1024;
    __half* Ch = g_Vthi + (size_t)m * PM;

    hgemm(Ah, Bh, 1, 1024, 1024, 1024,
        [=](int r, int c, float v0, float v1) {
            const float bb = bias[r];
            size_t o = (size_t)r * 8192 + c;
            *reinterpret_cast<__half2*>(Ch + o) =
                __halves2half2(__float2half_rn(v0 + bb), __float2half_rn(v1 + bb));
        });
}

// ---------------------------------------------------------------------------
// scores[z] = Q[z] @ K[z]^T * scale (fp16 out).  z = m*4+b.  M=N=2048, K=1024
// ---------------------------------------------------------------------------
__global__ __launch_bounds__(256)
void scores_kernel()
{
    const int z = blockIdx.z;
    const size_t off = ((size_t)(z >> 2) * BS + (size_t)(z & 3) * SVAL) * DVAL;
    const __half* Ah[1] = {g_Qhi + off};
    const __half* Bh[1] = {g_Khi + off};
    __half* Sp = g_Sc + (size_t)z * SVAL * SVAL;

    hgemm(Ah, Bh, 1, 1024, 1024, 1024,
        [=](int r, int c, float v0, float v1) {
            *reinterpret_cast<__half2*>(Sp + (size_t)r * SVAL + c) =
                __halves2half2(__float2half_rn(v0 * 0.03125f),
                               __float2half_rn(v1 * 0.03125f));
        });
}

// ---------------------------------------------------------------------------
// softmax rows of 2048: g_Sc (fp16) -> g_Phi (fp16)
// ---------------------------------------------------------------------------
__global__ __launch_bounds__(256)
void softmax_kernel()
{
    const size_t row = blockIdx.x;
    const __half* p = g_Sc + row * SVAL;
    const int tid = threadIdx.x;

    // 8 halves per thread (one uint4)
    uint4 raw = reinterpret_cast<const uint4*>(p)[tid];
    __half2 h2[4];
    memcpy(h2, &raw, 16);
    float vals[8];
#pragma unroll
    for (int i = 0; i < 4; i++) {
        float2 f = __half22float2(h2[i]);
        vals[i * 2] = f.x; vals[i * 2 + 1] = f.y;
    }

    float mx = vals[0];
#pragma unroll
    for (int i = 1; i < 8; i++) mx = fmaxf(mx, vals[i]);
    __shared__ float red[8];
#pragma unroll
    for (int o = 16; o; o >>= 1) mx = fmaxf(mx, __shfl_xor_sync(0xffffffffu, mx, o));
    if ((tid & 31) == 0) red[tid >> 5] = mx;
    __syncthreads();
    mx = red[0];
#pragma unroll
    for (int w = 1; w < 8; w++) mx = fmaxf(mx, red[w]);
    __syncthreads();

    float sum = 0.f;
#pragma unroll
    for (int i = 0; i < 8; i++) { vals[i] = __expf(vals[i] - mx); sum += vals[i]; }
#pragma unroll
    for (int o = 16; o; o >>= 1) sum += __shfl_xor_sync(0xffffffffu, sum, o);
    if ((tid & 31) == 0) red[tid >> 5] = sum;
    __syncthreads();
    sum = red[0];
#pragma unroll
    for (int w = 1; w < 8; w++) sum += red[w];
    const float inv = 1.0f / sum;

    alignas(16) __half h[8];
#pragma unroll
    for (int i = 0; i < 8; i++) h[i] = __float2half_rn(vals[i] * inv);
    reinterpret_cast<uint4*>(g_Phi + row * SVAL)[tid] = *reinterpret_cast<uint4*>(h);
}

// ---------------------------------------------------------------------------
// ctx[z] = P[z] @ Vt[(m+1)%3, b]^T.  M=2048(s), N=1024(d), K=2048
// ---------------------------------------------------------------------------
__global__ __launch_bounds__(256)
void ctx_kernel()
{
    const int z = blockIdx.z;
    const int m = z >> 2, b = z & 3;
    const int mn = (m + 1) % 3;
    const size_t aoff = (size_t)z * SVAL * SVAL;
    const size_t boff = (size_t)mn * PM + (size_t)b * SVAL;
    const __half* Ah[1] = {g_Phi + aoff};
    const __half* Bh[1] = {g_Vthi + boff};
    __half* Ch = g_Ctxhi + ((size_t)m * BS + (size_t)b * SVAL) * DVAL;

    hgemm(Ah, Bh, 1, 2048, 2048, 8192,
        [=](int r, int c, float v0, float v1) {
            size_t o = (size_t)r * DVAL + c;
            *reinterpret_cast<__half2*>(Ch + o) =
                __halves2half2(__float2half_rn(v0), __float2half_rn(v1));
        });
}

// ---------------------------------------------------------------------------
// out[m] = [X|Ctx][m] @ WoT[m]^T + bo.  M=8192, N=1024, K=2x1024 (2 segments)
// ---------------------------------------------------------------------------
__global__ __launch_bounds__(256)
void out_kernel(const float* __restrict__ bo, float* __restrict__ out)
{
    const int m = blockIdx.z;
    const size_t xo = (size_t)m * PM;
    const __half* Wh = g_WoThi + (size_t)m * 1024 * 2048;
    const __half* Ah[2] = {g_Xhi + xo, g_Ctxhi + xo};
    const __half* Bh[2] = {Wh, Wh + 1024};
    const float* bias = bo + m * 1024;
    float* o_m = out + (size_t)m * PM;
    float* gf  = out + (size_t)3 * PM;

    hgemm(Ah, Bh, 2, 1024, 1024, 2048,
        [=](int r, int c, float v0, float v1) {
            float2 f;
            f.x = v0 + bias[c];
            f.y = v1 + bias[c + 1];
            const size_t o1 = (size_t)r * DVAL + c;
            const int bb = r >> 11, ss = r & (SVAL - 1);
            const size_t o2 = ((size_t)bb * 3 * SVAL + (size_t)m * SVAL + ss) * DVAL + c;
            *reinterpret_cast<float2*>(o_m + o1) = f;
            *reinterpret_cast<float2*>(gf  + o2) = f;
        });
}

// ---------------------------------------------------------------------------
extern "C" void kernel_launch(void* const* d_in, const int* in_sizes, int n_in,
                              void* d_out, int out_size)
{
    const float* x1 = (const float*)d_in[0];
    const float* x2 = (const float*)d_in[1];
    const float* x3 = (const float*)d_in[2];
    const float* Wq = (const float*)d_in[3];
    const float* bq = (const float*)d_in[4];
    const float* Wk = (const float*)d_in[5];
    const float* bk = (const float*)d_in[6];
    const float* Wv = (const float*)d_in[7];
    const float* bv = (const float*)d_in[8];
    const float* Wo = (const float*)d_in[9];
    const float* bo = (const float*)d_in[10];
    float* out = (float*)d_out;

    // 72 KB dynamic SMEM opt-in (idempotent; not an allocation)
    cudaFuncSetAttribute(qk_proj,       cudaFuncAttributeMaxDynamicSharedMemorySize, GSMEM);
    cudaFuncSetAttribute(vt_proj,       cudaFuncAttributeMaxDynamicSharedMemorySize, GSMEM);
    cudaFuncSetAttribute(scores_kernel, cudaFuncAttributeMaxDynamicSharedMemorySize, GSMEM);
    cudaFuncSetAttribute(ctx_kernel,    cudaFuncAttributeMaxDynamicSharedMemorySize, GSMEM);
    cudaFuncSetAttribute(out_kernel,    cudaFuncAttributeMaxDynamicSharedMemorySize, GSMEM);

    // input conversions (destinations resolved in device code)
    conv_x<<<(unsigned)(3 * PM / 4 / 256), 256>>>(x1, x2, x3);
    {
        dim3 blk(32, 8);
        convT_sel<<<dim3(32, 32, 3), blk>>>(Wq, 0, 1024, 1024);
        convT_sel<<<dim3(32, 32, 3), blk>>>(Wk, 1, 1024, 1024);
        convT_sel<<<dim3(32, 32, 3), blk>>>(Wv, 2, 1024, 1024);
        convT_sel<<<dim3(32, 64, 3), blk>>>(Wo, 3, 2048, 1024);
    }

    qk_proj       <<<dim3(8, 64, 6),   256, GSMEM>>>(bq, bk);
    vt_proj       <<<dim3(64, 8, 3),   256, GSMEM>>>(bv);
    scores_kernel <<<dim3(16, 16, 12), 256, GSMEM>>>();
    softmax_kernel<<<3 * BVAL * SVAL,  256>>>();
    ctx_kernel    <<<dim3(8, 16, 12),  256, GSMEM>>>();
    out_kernel    <<<dim3(8, 64, 3),   256, GSMEM>>>(bo, out);
}